// round 1
// baseline (speedup 1.0000x reference)
#include <cuda_runtime.h>

#define NN   4096
#define BB   256
#define EMB  16
#define HIDN 32
#define VOC  200
#define TT   128

// ---------------- scratch (device globals; no allocation) ----------------
static __device__ float g_h[(size_t)NN * BB * HIDN];     // 128 MB node states, [node][batch][32]
static __device__ float g_Wl[32 * 32];                   // fused leaf weights
static __device__ float g_bl[32];
static __device__ float g_La[VOC * 32];                  // leaf table (bias folded)
static __device__ float g_Lb[VOC * 32];
static __device__ float g_Pa[VOC * 32];                  // node pair table (node_b folded)
static __device__ float g_Pb[VOC * 32];
static __device__ float g_F[BB * 32];                    // first_notes @ ptr_w_top + ptr_b
static __device__ float g_Lt[(size_t)BB * TT * 32];      // lstm_out @ ptr_w_bot
static __device__ float g_v[32];                         // fused ff/tail vector
static __device__ float g_s;                             // fused ff/tail scalar
static __device__ int   g_cnt[NN];
static __device__ int   g_cur[NN];
static __device__ int   g_off[NN + 1];
static __device__ int   g_child[NN];

// ---------------- f32x2 helpers (Blackwell packed fp32) ----------------
__device__ __forceinline__ unsigned long long pack2(float lo, float hi) {
    unsigned long long r;
    asm("mov.b64 %0, {%1, %2};" : "=l"(r) : "r"(__float_as_uint(lo)), "r"(__float_as_uint(hi)));
    return r;
}
__device__ __forceinline__ void unpack2(unsigned long long v, float& lo, float& hi) {
    unsigned int a, b;
    asm("mov.b64 {%0, %1}, %2;" : "=r"(a), "=r"(b) : "l"(v));
    lo = __uint_as_float(a);
    hi = __uint_as_float(b);
}
__device__ __forceinline__ void fma2(unsigned long long& d, unsigned long long a, unsigned long long b) {
    asm("fma.rn.f32x2 %0, %1, %2, %0;" : "+l"(d) : "l"(a), "l"(b));
}

// ---------------- small fusions ----------------
__global__ void k_fuse(const float* lw1, const float* lb1, const float* lw2, const float* lb2,
                       const float* fw1, const float* fb1, const float* fw2, const float* fb2,
                       const float* tw, const float* tb) {
    __shared__ float u[32];
    int t = threadIdx.x;
    int i = t >> 5, j = t & 31;
    float s = 0.f;
    for (int k = 0; k < 32; k++) s += lw1[i * 32 + k] * lw2[k * 32 + j];
    g_Wl[t] = s;
    if (t < 32) {
        float bsum = lb2[t];
        for (int k = 0; k < 32; k++) bsum += lb1[k] * lw2[k * 32 + t];
        g_bl[t] = bsum;
        float uu = 0.f;
        for (int q = 0; q < 32; q++) uu += fw2[t * 32 + q] * tw[q];
        u[t] = uu;
    }
    __syncthreads();
    if (t < 32) {
        float vv = 0.f;
        for (int k = 0; k < 32; k++) vv += fw1[t * 32 + k] * u[k];
        g_v[t] = vv;
    }
    if (t == 0) {
        float ss = tb[0];
        for (int k = 0; k < 32; k++) ss += fb1[k] * u[k];
        for (int q = 0; q < 32; q++) ss += fb2[q] * tw[q];
        g_s = ss;
    }
}

__global__ void k_tables(const float* emb, const float* node_w, const float* node_b) {
    int v = blockIdx.x, j = threadIdx.x;
    float la = g_bl[j], lb = 0.f, pa = node_b[j], pb = 0.f;
    for (int e = 0; e < EMB; e++) {
        float ev = emb[v * EMB + e];
        la += ev * g_Wl[e * 32 + j];
        lb += ev * g_Wl[(EMB + e) * 32 + j];
        pa += ev * node_w[e * 32 + j];
        pb += ev * node_w[(EMB + e) * 32 + j];
    }
    g_La[v * 32 + j] = la;
    g_Lb[v * 32 + j] = lb;
    g_Pa[v * 32 + j] = pa;
    g_Pb[v * 32 + j] = pb;
}

__global__ void k_F(const float* fn, const float* pw, const float* pbias) {
    int b = blockIdx.x, j = threadIdx.x;
    float s = pbias[j];
    for (int k = 0; k < 64; k++) s += fn[b * 64 + k] * pw[k * 32 + j];
    g_F[b * 32 + j] = s;
}

__global__ void k_Lt(const float* lstm, const float* pw) {
    int r = blockIdx.x, j = threadIdx.x;
    float s = 0.f;
    for (int k = 0; k < 64; k++) s += lstm[(size_t)r * 64 + k] * pw[(64 + k) * 32 + j];
    g_Lt[(size_t)r * 32 + j] = s;
}

// ---------------- CSR build (local 4096-node tree, shared across batch) ----------------
__global__ void k_csr_zero() {
    int i = blockIdx.x * 256 + threadIdx.x;
    if (i < NN) { g_cnt[i] = 0; g_cur[i] = 0; }
}
__global__ void k_csr_count(const int* parent) {
    int c = blockIdx.x * 256 + threadIdx.x;
    if (c >= 1 && c < NN) atomicAdd(&g_cnt[parent[c]], 1);
}
__global__ void k_csr_scan() {
    __shared__ int sm[1024];
    int t = threadIdx.x;
    int c0 = g_cnt[4 * t], c1 = g_cnt[4 * t + 1], c2 = g_cnt[4 * t + 2], c3 = g_cnt[4 * t + 3];
    int s = c0 + c1 + c2 + c3;
    sm[t] = s;
    __syncthreads();
    for (int off = 1; off < 1024; off <<= 1) {
        int v = (t >= off) ? sm[t - off] : 0;
        __syncthreads();
        sm[t] += v;
        __syncthreads();
    }
    int excl = sm[t] - s;
    g_off[4 * t]     = excl;
    g_off[4 * t + 1] = excl + c0;
    g_off[4 * t + 2] = excl + c0 + c1;
    g_off[4 * t + 3] = excl + c0 + c1 + c2;
    if (t == 1023) g_off[NN] = sm[t];
}
__global__ void k_csr_fill(const int* parent) {
    int c = blockIdx.x * 256 + threadIdx.x;
    if (c >= 1 && c < NN) {
        int p = parent[c];
        int pos = atomicAdd(&g_cur[p], 1);
        g_child[g_off[p] + pos] = c;
    }
}

// ---------------- leaf init ----------------
__global__ void __launch_bounds__(BB) k_leaf(const int* kind, const int* height,
                                             const int* tok_a, const int* tok_b,
                                             const int* ptr_time) {
    int p = blockIdx.x;
    if (height[p] != 0) return;
    int b = threadIdx.x;
    int kd = kind[p];
    float4 r[8];
    if (kd == 0) {
        int ta = tok_a[(size_t)b * NN + p];
        int tb = tok_b[(size_t)b * NN + p];
        const float4* A  = (const float4*)(g_La + ta * 32);
        const float4* Bv = (const float4*)(g_Lb + tb * 32);
        #pragma unroll
        for (int q = 0; q < 8; q++) {
            float4 x = A[q], y = Bv[q];
            r[q] = make_float4(x.x + y.x, x.y + y.y, x.z + y.z, x.w + y.w);
        }
    } else if (kd == 1) {
        int tm = ptr_time[(size_t)b * NN + p];
        const float4* A  = (const float4*)(g_F + b * 32);
        const float4* Bv = (const float4*)(g_Lt + ((size_t)b * TT + tm) * 32);
        #pragma unroll
        for (int q = 0; q < 8; q++) {
            float4 x = A[q], y = Bv[q];
            r[q] = make_float4(x.x + y.x, x.y + y.y, x.z + y.z, x.w + y.w);
        }
    } else {
        #pragma unroll
        for (int q = 0; q < 8; q++) r[q] = make_float4(0.f, 0.f, 0.f, 0.f);
    }
    float4* dst = (float4*)(g_h + ((size_t)p * BB + b) * HIDN);
    #pragma unroll
    for (int q = 0; q < 8; q++) dst[q] = r[q];
}

// ---------------- level update (heights 1..5) ----------------
__global__ void __launch_bounds__(BB) k_level(const int* __restrict__ height,
                                              const int* __restrict__ tok_a,
                                              const int* __restrict__ tok_b,
                                              const float* __restrict__ node_w,
                                              int lvl) {
    int p = blockIdx.x;
    if (height[p] != lvl) return;
    __shared__ __align__(16) unsigned long long Wsh[32 * 16];  // bottom half of node_w, packed pairs
    int t = threadIdx.x;
    for (int i = t; i < 512; i += BB) {
        int k = i >> 4, j = i & 15;
        Wsh[i] = pack2(node_w[(32 + k) * 32 + 2 * j], node_w[(32 + k) * 32 + 2 * j + 1]);
    }
    __syncthreads();
    int b = t;
    float acc[32];
    #pragma unroll
    for (int i = 0; i < 32; i++) acc[i] = 0.f;
    int cs = g_off[p], ce = g_off[p + 1];
    for (int ci = cs; ci < ce; ci++) {
        int c = g_child[ci];
        const float4* src = (const float4*)(g_h + ((size_t)c * BB + b) * HIDN);
        #pragma unroll
        for (int q = 0; q < 8; q++) {
            float4 v = src[q];
            acc[4 * q] += v.x; acc[4 * q + 1] += v.y; acc[4 * q + 2] += v.z; acc[4 * q + 3] += v.w;
        }
    }
    int ta = tok_a[(size_t)b * NN + p];
    int tb = tok_b[(size_t)b * NN + p];
    const float4* pa = (const float4*)(g_Pa + ta * 32);
    const float4* pb = (const float4*)(g_Pb + tb * 32);
    unsigned long long o[16];
    #pragma unroll
    for (int q = 0; q < 8; q++) {
        float4 x = pa[q], y = pb[q];
        o[2 * q]     = pack2(x.x + y.x, x.y + y.y);
        o[2 * q + 1] = pack2(x.z + y.z, x.w + y.w);
    }
    #pragma unroll
    for (int k = 0; k < 32; k++) {
        unsigned long long a2 = pack2(acc[k], acc[k]);
        const ulonglong2* w2 = (const ulonglong2*)(Wsh + k * 16);
        #pragma unroll
        for (int j2 = 0; j2 < 8; j2++) {
            ulonglong2 ww = w2[j2];
            fma2(o[2 * j2], a2, ww.x);
            fma2(o[2 * j2 + 1], a2, ww.y);
        }
    }
    float4* dst = (float4*)(g_h + ((size_t)p * BB + b) * HIDN);
    #pragma unroll
    for (int q = 0; q < 8; q++) {
        float l0, h0, l1, h1;
        unpack2(o[2 * q], l0, h0);
        unpack2(o[2 * q + 1], l1, h1);
        dst[q] = make_float4(fmaxf(l0, 0.f), fmaxf(h0, 0.f), fmaxf(l1, 0.f), fmaxf(h1, 0.f));
    }
}

// ---------------- root (height 6 = node 0) + fused ff/tail readout ----------------
__global__ void __launch_bounds__(BB) k_root(const int* __restrict__ tok_a,
                                             const int* __restrict__ tok_b,
                                             const float* __restrict__ node_w,
                                             float* __restrict__ out) {
    int b = blockIdx.x, t = threadIdx.x;
    int f = t & 31, g = t >> 5;
    __shared__ float part[8][32];
    __shared__ float csum[32];
    float a = 0.f;
    int cs = g_off[0], ce = g_off[1];
    for (int ci = cs + g; ci < ce; ci += 8) {
        int c = g_child[ci];
        a += g_h[((size_t)c * BB + b) * HIDN + f];
    }
    part[g][f] = a;
    __syncthreads();
    if (g == 0) {
        float s = part[0][f] + part[1][f] + part[2][f] + part[3][f]
                + part[4][f] + part[5][f] + part[6][f] + part[7][f];
        csum[f] = s;
    }
    __syncthreads();
    if (t < 32) {
        int ta = tok_a[(size_t)b * NN];
        int tb = tok_b[(size_t)b * NN];
        float o = g_Pa[ta * 32 + t] + g_Pb[tb * 32 + t];
        #pragma unroll
        for (int k = 0; k < 32; k++) o += csum[k] * node_w[(32 + k) * 32 + t];
        o = fmaxf(o, 0.f) * g_v[t];
        #pragma unroll
        for (int off = 16; off; off >>= 1) o += __shfl_down_sync(0xffffffffu, o, off);
        if (t == 0) out[b] = o + g_s;
    }
}

// ---------------- launch ----------------
extern "C" void kernel_launch(void* const* d_in, const int* in_sizes, int n_in,
                              void* d_out, int out_size) {
    const int*   kind        = (const int*)d_in[0];
    const int*   height      = (const int*)d_in[1];
    const int*   parent      = (const int*)d_in[2];
    const int*   tok_a       = (const int*)d_in[3];
    const int*   tok_b       = (const int*)d_in[4];
    const int*   ptr_time    = (const int*)d_in[5];
    const float* first_notes = (const float*)d_in[6];
    const float* lstm_out    = (const float*)d_in[7];
    const float* embedding   = (const float*)d_in[8];
    const float* leaf_w1     = (const float*)d_in[9];
    const float* leaf_b1     = (const float*)d_in[10];
    const float* leaf_w2     = (const float*)d_in[11];
    const float* leaf_b2     = (const float*)d_in[12];
    const float* node_w      = (const float*)d_in[13];
    const float* node_b      = (const float*)d_in[14];
    const float* ptr_w       = (const float*)d_in[15];
    const float* ptr_b       = (const float*)d_in[16];
    const float* ff_w1       = (const float*)d_in[17];
    const float* ff_b1       = (const float*)d_in[18];
    const float* ff_w2       = (const float*)d_in[19];
    const float* ff_b2       = (const float*)d_in[20];
    const float* tail_w      = (const float*)d_in[21];
    const float* tail_b      = (const float*)d_in[22];
    float* out = (float*)d_out;

    k_fuse<<<1, 1024>>>(leaf_w1, leaf_b1, leaf_w2, leaf_b2,
                        ff_w1, ff_b1, ff_w2, ff_b2, tail_w, tail_b);
    k_tables<<<VOC, 32>>>(embedding, node_w, node_b);
    k_F<<<BB, 32>>>(first_notes, ptr_w, ptr_b);
    k_Lt<<<BB * TT, 32>>>(lstm_out, ptr_w);
    k_csr_zero<<<NN / 256, 256>>>();
    k_csr_count<<<NN / 256, 256>>>(parent);
    k_csr_scan<<<1, 1024>>>();
    k_csr_fill<<<NN / 256, 256>>>(parent);
    k_leaf<<<NN, BB>>>(kind, height, tok_a, tok_b, ptr_time);
    for (int lvl = 1; lvl <= 5; lvl++)
        k_level<<<NN, BB>>>(height, tok_a, tok_b, node_w, lvl);
    k_root<<<BB, BB>>>(tok_a, tok_b, node_w, out);
}

// round 2
// speedup vs baseline: 1.0426x; 1.0426x over previous
#include <cuda_runtime.h>

#define NN   4096
#define BB   256
#define EMB  16
#define VOC  200
#define TT   128
#define LVGRID 296

// ---------------- scratch (device globals; no allocation) ----------------
static __device__ float4 g_h4[(size_t)NN * 8 * BB];      // 134MB node states, [node][q][batch] float4
static __device__ float4 g_part4[32 * 8 * BB];           // root partial sums
static __device__ float g_Wl[32 * 32];                   // fused leaf weights
static __device__ float g_bl[32];
static __device__ float g_La[VOC * 32];                  // leaf tables (bias folded)
static __device__ float g_Lb[VOC * 32];
static __device__ float g_Pa[VOC * 32];                  // node pair tables (node_b folded)
static __device__ float g_Pb[VOC * 32];
static __device__ float g_F[BB * 32];                    // first_notes @ ptr_w_top + ptr_b
static __device__ float g_Lt[(size_t)BB * TT * 32];      // lstm_out @ ptr_w_bot
static __device__ float g_v[32];                         // fused ff/tail vector
static __device__ float g_s;                             // fused ff/tail scalar
static __device__ int   g_cnt[NN];
static __device__ int   g_cur[NN];
static __device__ int   g_off[NN + 1];
static __device__ int   g_child[NN];
static __device__ int   g_lvcnt[8];
static __device__ int   g_lvnodes[5 * NN];
static __device__ int   g_tA[NN * BB];                   // transposed tokens [p][b]
static __device__ int   g_tB[NN * BB];
static __device__ int   g_tP[NN * BB];

// ---------------- f32x2 helpers (Blackwell packed fp32) ----------------
__device__ __forceinline__ unsigned long long pack2(float lo, float hi) {
    unsigned long long r;
    asm("mov.b64 %0, {%1, %2};" : "=l"(r) : "r"(__float_as_uint(lo)), "r"(__float_as_uint(hi)));
    return r;
}
__device__ __forceinline__ void unpack2(unsigned long long v, float& lo, float& hi) {
    unsigned int a, b;
    asm("mov.b64 {%0, %1}, %2;" : "=r"(a), "=r"(b) : "l"(v));
    lo = __uint_as_float(a);
    hi = __uint_as_float(b);
}
__device__ __forceinline__ void fma2(unsigned long long& d, unsigned long long a, unsigned long long b) {
    asm("fma.rn.f32x2 %0, %1, %2, %0;" : "+l"(d) : "l"(a), "l"(b));
}

// ---------------- small fusions + scratch zeroing ----------------
__global__ void k_fuse(const float* lw1, const float* lb1, const float* lw2, const float* lb2,
                       const float* fw1, const float* fb1, const float* fw2, const float* fb2,
                       const float* tw, const float* tb) {
    __shared__ float u[32];
    int t = threadIdx.x;
    for (int i = t; i < NN; i += 1024) { g_cnt[i] = 0; g_cur[i] = 0; }
    if (t < 8) g_lvcnt[t] = 0;
    int i = t >> 5, j = t & 31;
    float s = 0.f;
    for (int k = 0; k < 32; k++) s += lw1[i * 32 + k] * lw2[k * 32 + j];
    g_Wl[t] = s;
    if (t < 32) {
        float bsum = lb2[t];
        for (int k = 0; k < 32; k++) bsum += lb1[k] * lw2[k * 32 + t];
        g_bl[t] = bsum;
        float uu = 0.f;
        for (int q = 0; q < 32; q++) uu += fw2[t * 32 + q] * tw[q];
        u[t] = uu;
    }
    __syncthreads();
    if (t < 32) {
        float vv = 0.f;
        for (int k = 0; k < 32; k++) vv += fw1[t * 32 + k] * u[k];
        g_v[t] = vv;
    }
    if (t == 0) {
        float ss = tb[0];
        for (int k = 0; k < 32; k++) ss += fb1[k] * u[k];
        for (int q = 0; q < 32; q++) ss += fb2[q] * tw[q];
        g_s = ss;
    }
}

__global__ void k_tables(const float* emb, const float* node_w, const float* node_b) {
    int v = blockIdx.x, j = threadIdx.x;
    float la = g_bl[j], lb = 0.f, pa = node_b[j], pb = 0.f;
    for (int e = 0; e < EMB; e++) {
        float ev = emb[v * EMB + e];
        la += ev * g_Wl[e * 32 + j];
        lb += ev * g_Wl[(EMB + e) * 32 + j];
        pa += ev * node_w[e * 32 + j];
        pb += ev * node_w[(EMB + e) * 32 + j];
    }
    g_La[v * 32 + j] = la;
    g_Lb[v * 32 + j] = lb;
    g_Pa[v * 32 + j] = pa;
    g_Pb[v * 32 + j] = pb;
}

__global__ void k_F(const float* fn, const float* pw, const float* pbias) {
    int b = blockIdx.x, j = threadIdx.x;
    float s = pbias[j];
    for (int k = 0; k < 64; k++) s += fn[b * 64 + k] * pw[k * 32 + j];
    g_F[b * 32 + j] = s;
}

// ---------------- Lt precompute: [B*T, 64] @ [64, 32], register-blocked ----------------
__global__ void __launch_bounds__(256) k_Lt(const float* __restrict__ lstm,
                                            const float* __restrict__ pw) {
    __shared__ float lssh[64 * 68];   // 64 rows, padded stride 68
    __shared__ float pwT[32 * 68];    // transposed bottom of ptr_w, padded
    int t = threadIdx.x;
    for (int i = t; i < 2048; i += 256) {
        int k = i >> 5, j2 = i & 31;
        pwT[j2 * 68 + k] = pw[2048 + i];
    }
    size_t base = (size_t)blockIdx.x * 64 * 64;
    for (int i = t; i < 4096; i += 256)
        lssh[(i >> 6) * 68 + (i & 63)] = lstm[base + i];
    __syncthreads();
    int w = t >> 5, j = t & 31;
    float s[8];
    #pragma unroll
    for (int r = 0; r < 8; r++) s[r] = 0.f;
    #pragma unroll
    for (int k4 = 0; k4 < 64; k4 += 4) {
        float4 wv = *(const float4*)(pwT + j * 68 + k4);
        #pragma unroll
        for (int r = 0; r < 8; r++) {
            float4 lv = *(const float4*)(lssh + (w * 8 + r) * 68 + k4);
            s[r] += lv.x * wv.x + lv.y * wv.y + lv.z * wv.z + lv.w * wv.w;
        }
    }
    int row0 = blockIdx.x * 64 + w * 8;
    #pragma unroll
    for (int r = 0; r < 8; r++)
        g_Lt[(size_t)(row0 + r) * 32 + j] = s[r];
}

// ---------------- token transpose [b][p] -> [p][b] ----------------
__global__ void k_tr(const int* __restrict__ a, const int* __restrict__ b,
                     const int* __restrict__ c) {
    __shared__ int tile[32][33];
    const int* src = blockIdx.z == 0 ? a : (blockIdx.z == 1 ? b : c);
    int* dst = blockIdx.z == 0 ? g_tA : (blockIdx.z == 1 ? g_tB : g_tP);
    int p0 = blockIdx.x * 32, b0 = blockIdx.y * 32;
    tile[threadIdx.y][threadIdx.x] = src[(size_t)(b0 + threadIdx.y) * NN + p0 + threadIdx.x];
    __syncthreads();
    dst[(size_t)(p0 + threadIdx.y) * BB + b0 + threadIdx.x] = tile[threadIdx.x][threadIdx.y];
}

// ---------------- CSR build + per-level node lists ----------------
__global__ void k_csr_count(const int* parent) {
    int c = blockIdx.x * 256 + threadIdx.x;
    if (c >= 1 && c < NN) atomicAdd(&g_cnt[parent[c]], 1);
}
__global__ void k_csr_scan() {
    __shared__ int sm[1024];
    int t = threadIdx.x;
    int c0 = g_cnt[4 * t], c1 = g_cnt[4 * t + 1], c2 = g_cnt[4 * t + 2], c3 = g_cnt[4 * t + 3];
    int s = c0 + c1 + c2 + c3;
    sm[t] = s;
    __syncthreads();
    for (int off = 1; off < 1024; off <<= 1) {
        int v = (t >= off) ? sm[t - off] : 0;
        __syncthreads();
        sm[t] += v;
        __syncthreads();
    }
    int excl = sm[t] - s;
    g_off[4 * t]     = excl;
    g_off[4 * t + 1] = excl + c0;
    g_off[4 * t + 2] = excl + c0 + c1;
    g_off[4 * t + 3] = excl + c0 + c1 + c2;
    if (t == 1023) g_off[NN] = sm[t];
}
__global__ void k_csr_fill(const int* parent) {
    int c = blockIdx.x * 256 + threadIdx.x;
    if (c >= 1 && c < NN) {
        int p = parent[c];
        int pos = atomicAdd(&g_cur[p], 1);
        g_child[g_off[p] + pos] = c;
    }
}
__global__ void k_lvbuild(const int* height) {
    int p = blockIdx.x * 256 + threadIdx.x;
    if (p < NN) {
        int h = height[p];
        if (h >= 1 && h <= 5) {
            int i = atomicAdd(&g_lvcnt[h], 1);
            g_lvnodes[(h - 1) * NN + i] = p;
        }
    }
}

// ---------------- leaf init ----------------
__global__ void __launch_bounds__(BB) k_leaf(const int* __restrict__ kind,
                                             const int* __restrict__ height) {
    int p = blockIdx.x;
    if (height[p] != 0) return;
    int b = threadIdx.x;
    int kd = kind[p];
    float4 r[8];
    if (kd == 0) {
        int ta = g_tA[p * BB + b];
        int tb = g_tB[p * BB + b];
        const float4* A  = (const float4*)(g_La + ta * 32);
        const float4* Bv = (const float4*)(g_Lb + tb * 32);
        #pragma unroll
        for (int q = 0; q < 8; q++) {
            float4 x = A[q], y = Bv[q];
            r[q] = make_float4(x.x + y.x, x.y + y.y, x.z + y.z, x.w + y.w);
        }
    } else if (kd == 1) {
        int tm = g_tP[p * BB + b];
        const float4* A  = (const float4*)(g_F + b * 32);
        const float4* Bv = (const float4*)(g_Lt + ((size_t)b * TT + tm) * 32);
        #pragma unroll
        for (int q = 0; q < 8; q++) {
            float4 x = A[q], y = Bv[q];
            r[q] = make_float4(x.x + y.x, x.y + y.y, x.z + y.z, x.w + y.w);
        }
    } else {
        #pragma unroll
        for (int q = 0; q < 8; q++) r[q] = make_float4(0.f, 0.f, 0.f, 0.f);
    }
    float4* dst = g_h4 + (size_t)p * 8 * BB + b;
    #pragma unroll
    for (int q = 0; q < 8; q++) dst[q * BB] = r[q];
}

// ---------------- level update (heights 1..5), smem tables + f32x2 matvec ----------------
__global__ void __launch_bounds__(BB) k_level(const float* __restrict__ node_w, int lvl) {
    extern __shared__ float dsm[];
    float* Pash = dsm;           // 200*36
    float* Pbsh = dsm + 7200;    // 200*36
    __shared__ __align__(16) ulonglong2 Wsh[32 * 8];
    int t = threadIdx.x;
    for (int i = t; i < 6400; i += BB) {
        int v = i >> 5, j = i & 31;
        Pash[v * 36 + j] = g_Pa[i];
        Pbsh[v * 36 + j] = g_Pb[i];
    }
    {
        const ulonglong2* wsrc = (const ulonglong2*)(node_w + 1024);
        Wsh[t] = wsrc[t];   // 256 ulonglong2 = 1024 floats (bottom half of node_w)
    }
    __syncthreads();
    int cnt = g_lvcnt[lvl];
    int b = t;
    for (int ni = blockIdx.x; ni < cnt; ni += LVGRID) {
        int p = g_lvnodes[(lvl - 1) * NN + ni];
        float acc[32];
        #pragma unroll
        for (int i = 0; i < 32; i++) acc[i] = 0.f;
        int cs = g_off[p], ce = g_off[p + 1];
        for (int ci = cs; ci < ce; ci++) {
            int c = g_child[ci];
            const float4* src = g_h4 + (size_t)c * 8 * BB + b;
            #pragma unroll
            for (int q = 0; q < 8; q++) {
                float4 v = src[q * BB];
                acc[4 * q] += v.x; acc[4 * q + 1] += v.y;
                acc[4 * q + 2] += v.z; acc[4 * q + 3] += v.w;
            }
        }
        int ta = g_tA[p * BB + b];
        int tb = g_tB[p * BB + b];
        const float4* pa = (const float4*)(Pash + ta * 36);
        const float4* pb = (const float4*)(Pbsh + tb * 36);
        unsigned long long o2[16];
        #pragma unroll
        for (int q = 0; q < 8; q++) {
            float4 x = pa[q], y = pb[q];
            o2[2 * q]     = pack2(x.x + y.x, x.y + y.y);
            o2[2 * q + 1] = pack2(x.z + y.z, x.w + y.w);
        }
        #pragma unroll
        for (int k = 0; k < 32; k++) {
            unsigned long long a2 = pack2(acc[k], acc[k]);
            #pragma unroll
            for (int j2 = 0; j2 < 8; j2++) {
                ulonglong2 w = Wsh[k * 8 + j2];
                fma2(o2[2 * j2], a2, w.x);
                fma2(o2[2 * j2 + 1], a2, w.y);
            }
        }
        float4* dst = g_h4 + (size_t)p * 8 * BB + b;
        #pragma unroll
        for (int q = 0; q < 8; q++) {
            float l0, h0, l1, h1;
            unpack2(o2[2 * q], l0, h0);
            unpack2(o2[2 * q + 1], l1, h1);
            dst[q * BB] = make_float4(fmaxf(l0, 0.f), fmaxf(h0, 0.f),
                                      fmaxf(l1, 0.f), fmaxf(h1, 0.f));
        }
    }
}

// ---------------- root: 32-way partial child sum + finish ----------------
__global__ void __launch_bounds__(BB) k_rootsum() {
    int b = threadIdx.x;
    float acc[32];
    #pragma unroll
    for (int i = 0; i < 32; i++) acc[i] = 0.f;
    int cs = g_off[0], ce = g_off[1];
    for (int ci = cs + blockIdx.x; ci < ce; ci += 32) {
        int c = g_child[ci];
        const float4* src = g_h4 + (size_t)c * 8 * BB + b;
        #pragma unroll
        for (int q = 0; q < 8; q++) {
            float4 v = src[q * BB];
            acc[4 * q] += v.x; acc[4 * q + 1] += v.y;
            acc[4 * q + 2] += v.z; acc[4 * q + 3] += v.w;
        }
    }
    float4* dst = g_part4 + (size_t)blockIdx.x * 8 * BB + b;
    #pragma unroll
    for (int q = 0; q < 8; q++)
        dst[q * BB] = make_float4(acc[4 * q], acc[4 * q + 1], acc[4 * q + 2], acc[4 * q + 3]);
}

__global__ void k_rootfin(const float* __restrict__ node_w, float* __restrict__ out) {
    int b = blockIdx.x * 32 + threadIdx.x;
    float cs[32];
    #pragma unroll
    for (int i = 0; i < 32; i++) cs[i] = 0.f;
    for (int i = 0; i < 32; i++) {
        const float4* src = g_part4 + (size_t)i * 8 * BB + b;
        #pragma unroll
        for (int q = 0; q < 8; q++) {
            float4 v = src[q * BB];
            cs[4 * q] += v.x; cs[4 * q + 1] += v.y;
            cs[4 * q + 2] += v.z; cs[4 * q + 3] += v.w;
        }
    }
    int ta = g_tA[b];
    int tb = g_tB[b];
    float o[32];
    #pragma unroll
    for (int j = 0; j < 32; j++) o[j] = g_Pa[ta * 32 + j] + g_Pb[tb * 32 + j];
    for (int k = 0; k < 32; k++) {
        float a = cs[k];
        #pragma unroll
        for (int j = 0; j < 32; j++) o[j] += a * node_w[(32 + k) * 32 + j];
    }
    float val = 0.f;
    #pragma unroll
    for (int j = 0; j < 32; j++) val += fmaxf(o[j], 0.f) * g_v[j];
    out[b] = val + g_s;
}

// ---------------- launch ----------------
extern "C" void kernel_launch(void* const* d_in, const int* in_sizes, int n_in,
                              void* d_out, int out_size) {
    const int*   kind        = (const int*)d_in[0];
    const int*   height      = (const int*)d_in[1];
    const int*   parent      = (const int*)d_in[2];
    const int*   tok_a       = (const int*)d_in[3];
    const int*   tok_b       = (const int*)d_in[4];
    const int*   ptr_time    = (const int*)d_in[5];
    const float* first_notes = (const float*)d_in[6];
    const float* lstm_out    = (const float*)d_in[7];
    const float* embedding   = (const float*)d_in[8];
    const float* leaf_w1     = (const float*)d_in[9];
    const float* leaf_b1     = (const float*)d_in[10];
    const float* leaf_w2     = (const float*)d_in[11];
    const float* leaf_b2     = (const float*)d_in[12];
    const float* node_w      = (const float*)d_in[13];
    const float* node_b      = (const float*)d_in[14];
    const float* ptr_w       = (const float*)d_in[15];
    const float* ptr_b       = (const float*)d_in[16];
    const float* ff_w1       = (const float*)d_in[17];
    const float* ff_b1       = (const float*)d_in[18];
    const float* ff_w2       = (const float*)d_in[19];
    const float* ff_b2       = (const float*)d_in[20];
    const float* tail_w      = (const float*)d_in[21];
    const float* tail_b      = (const float*)d_in[22];
    float* out = (float*)d_out;

    cudaFuncSetAttribute(k_level, cudaFuncAttributeMaxDynamicSharedMemorySize, 57600);

    k_fuse<<<1, 1024>>>(leaf_w1, leaf_b1, leaf_w2, leaf_b2,
                        ff_w1, ff_b1, ff_w2, ff_b2, tail_w, tail_b);
    k_tables<<<VOC, 32>>>(embedding, node_w, node_b);
    k_F<<<BB, 32>>>(first_notes, ptr_w, ptr_b);
    k_Lt<<<BB * TT / 64, 256>>>(lstm_out, ptr_w);
    k_tr<<<dim3(NN / 32, BB / 32, 3), dim3(32, 32)>>>(tok_a, tok_b, ptr_time);
    k_csr_count<<<NN / 256, 256>>>(parent);
    k_csr_scan<<<1, 1024>>>();
    k_csr_fill<<<NN / 256, 256>>>(parent);
    k_lvbuild<<<NN / 256, 256>>>(height);
    k_leaf<<<NN, BB>>>(kind, height);
    for (int lvl = 1; lvl <= 5; lvl++)
        k_level<<<LVGRID, BB, 57600>>>(node_w, lvl);
    k_rootsum<<<32, BB>>>();
    k_rootfin<<<BB / 32, 32>>>(node_w, out);
}